// round 13
// baseline (speedup 1.0000x reference)
#include <cuda_runtime.h>

#define NS 2048
#define ND 2048
#define NK 6
#define NT 192   // 6 warps: warp k handles direction k. No smem, no barriers.

__global__ __launch_bounds__(NT, 4)
void query_token_probe_kernel(const float* __restrict__ hs,
                              const float* __restrict__ W,
                              const float* __restrict__ bias,
                              const int*   __restrict__ input_ids,
                              const int*   __restrict__ attn_mask,
                              const int*   __restrict__ token_ids,
                              float*       __restrict__ out) {
    const int b    = blockIdx.x;        // 0..31 batch
    const int kdir = threadIdx.x >> 5;  // 0..5  direction (one warp each)
    const int lid  = threadIdx.x & 31;

    const int   tkv = token_ids[kdir];
    const float bk  = bias[kdir];

    // --- Phase 1: each warp scans this batch's 2048 ids + 2048 mask.
    //     The 6 warps request the SAME lines -> L1tex miss-merge: ~1x L2 traffic.
    //     16+16 independent int4 loads per lane -> one round trip. ---
    const int4* __restrict__ mbase = (const int4*)(attn_mask + (size_t)b * NS);
    const int4* __restrict__ ibase = (const int4*)(input_ids + (size_t)b * NS);

    int lv = -1;   // last valid position seen by this lane
    int lm = -1;   // last position matching tkv

#pragma unroll
    for (int j = 0; j < 16; j++) {
        const int4 m4 = mbase[j * 32 + lid];
        const int4 i4 = ibase[j * 32 + lid];
        const int  p0 = (j * 32 + lid) * 4;
        // positions ascend with j and component -> overwrite == running max
        if (m4.x > 0) { lv = p0 + 0; if (i4.x == tkv) lm = p0 + 0; }
        if (m4.y > 0) { lv = p0 + 1; if (i4.y == tkv) lm = p0 + 1; }
        if (m4.z > 0) { lv = p0 + 2; if (i4.z == tkv) lm = p0 + 2; }
        if (m4.w > 0) { lv = p0 + 3; if (i4.w == tkv) lm = p0 + 3; }
    }

    // two single-instruction warp reduces; no cross-warp communication needed
    const int lastv = __reduce_max_sync(0xffffffffu, lv);
    int       fp    = __reduce_max_sync(0xffffffffu, lm);
    if (fp < 0) fp = lastv;
    const int  pos       = fp < 0 ? 0 : (fp > NS - 1 ? NS - 1 : fp);
    const bool has_valid = (lastv >= 0);

    // --- Phase 2: warp does dot(hs[b,pos,:], W[kdir]).
    //     16 hs + 16 W independent loads -> one round trip. ---
    const float4* __restrict__ hrow =
        (const float4*)(hs + ((size_t)b * NS + (size_t)pos) * ND);
    const float4* __restrict__ wrow = (const float4*)(W + (size_t)kdir * ND);

    float s0 = 0.f, s1 = 0.f;
#pragma unroll
    for (int j = 0; j < 16; j += 2) {
        const float4 h0 = hrow[j * 32 + lid];
        const float4 w0 = wrow[j * 32 + lid];
        const float4 h1 = hrow[(j + 1) * 32 + lid];
        const float4 w1 = wrow[(j + 1) * 32 + lid];
        s0 += h0.x * w0.x + h0.y * w0.y + h0.z * w0.z + h0.w * w0.w;
        s1 += h1.x * w1.x + h1.y * w1.y + h1.z * w1.z + h1.w * w1.w;
    }
    float sum = s0 + s1;
#pragma unroll
    for (int off = 16; off > 0; off >>= 1)
        sum += __shfl_xor_sync(0xffffffffu, sum, off);

    if (lid == 0)
        out[b * NK + kdir] = has_valid ? (sum + bk) : 0.f;
}

extern "C" void kernel_launch(void* const* d_in, const int* in_sizes, int n_in,
                              void* d_out, int out_size) {
    const float* hs        = (const float*)d_in[0];
    const float* W         = (const float*)d_in[1];
    const float* bias      = (const float*)d_in[2];
    const int*   input_ids = (const int*)d_in[3];
    const int*   attn_mask = (const int*)d_in[4];
    const int*   token_ids = (const int*)d_in[5];
    float*       out       = (float*)d_out;

    query_token_probe_kernel<<<32, NT>>>(hs, W, bias, input_ids, attn_mask,
                                         token_ids, out);
}

// round 14
// speedup vs baseline: 1.0385x; 1.0385x over previous
#include <cuda_runtime.h>

#define NS 2048
#define ND 2048
#define NK 6
#define NT 256   // 8 warps
#define NW (NT / 32)

__global__ __launch_bounds__(NT, 2)
void query_token_probe_kernel(const float* __restrict__ hs,
                              const float* __restrict__ W,
                              const float* __restrict__ bias,
                              const int*   __restrict__ input_ids,
                              const int*   __restrict__ attn_mask,
                              const int*   __restrict__ token_ids,
                              float*       __restrict__ out) {
    const int kdir = blockIdx.x;   // 0..5  direction
    const int b    = blockIdx.y;   // 0..31 batch
    const int tid  = threadIdx.x;
    const int wid  = tid >> 5;
    const int lid  = tid & 31;

    __shared__ int s_part[2][NW];  // [lv | lm][warp]

    // this block's token id + bias (tiny scalar loads, overlap the big RT)
    const int   tkv = token_ids[kdir];
    const float bk  = bias[kdir];

    // --- Phase 1: 8 elements per thread, all 4 vector loads independent -> one RT ---
    const int4* mbase = (const int4*)(attn_mask + (size_t)b * NS);
    const int4* ibase = (const int4*)(input_ids + (size_t)b * NS);
    const int4 m4a = mbase[tid];
    const int4 i4a = ibase[tid];
    const int4 m4b = mbase[tid + NT];
    const int4 i4b = ibase[tid + NT];

    int lv = -1;   // last valid position this thread saw
    int lm = -1;   // last position matching tkv

    const int mv[8] = {m4a.x, m4a.y, m4a.z, m4a.w, m4b.x, m4b.y, m4b.z, m4b.w};
    const int iv[8] = {i4a.x, i4a.y, i4a.z, i4a.w, i4b.x, i4b.y, i4b.z, i4b.w};
#pragma unroll
    for (int j = 0; j < 8; j++) {
        const int p = (j < 4) ? (tid * 4 + j) : ((tid + NT) * 4 + (j - 4));
        if (mv[j] > 0) {
            lv = p;                       // p increasing in j -> overwrite == max
            if (iv[j] == tkv) lm = p;
        }
    }

    lv = __reduce_max_sync(0xffffffffu, lv);
    lm = __reduce_max_sync(0xffffffffu, lm);
    if (lid == 0) { s_part[0][wid] = lv; s_part[1][wid] = lm; }
    __syncthreads();                      // the ONLY barrier

    if (wid != 0) return;                 // warp 0 finishes alone

    // cross-warp max: 8 partials in lanes 0..7, one REDUX each
    const int pvv   = (lid < NW) ? s_part[0][lid] : -1;
    const int pv    = (lid < NW) ? s_part[1][lid] : -1;
    const int lastv = __reduce_max_sync(0xffffffffu, pvv);
    int       fp    = __reduce_max_sync(0xffffffffu, pv);
    if (fp < 0) fp = lastv;
    const int  pos       = fp < 0 ? 0 : (fp > NS - 1 ? NS - 1 : fp);
    const bool has_valid = (lastv >= 0);

    // --- Phase 2: full dot by warp 0: 16 hs + 16 W loads, one RT ---
    const float4* __restrict__ hrow =
        (const float4*)(hs + ((size_t)b * NS + (size_t)pos) * ND);
    const float4* __restrict__ wrow = (const float4*)(W + (size_t)kdir * ND);

    float s0 = 0.f, s1 = 0.f;
#pragma unroll
    for (int j = 0; j < 16; j += 2) {
        const float4 h0 = hrow[j * 32 + lid];
        const float4 w0 = wrow[j * 32 + lid];
        const float4 h1 = hrow[(j + 1) * 32 + lid];
        const float4 w1 = wrow[(j + 1) * 32 + lid];
        s0 += h0.x * w0.x + h0.y * w0.y + h0.z * w0.z + h0.w * w0.w;
        s1 += h1.x * w1.x + h1.y * w1.y + h1.z * w1.z + h1.w * w1.w;
    }
    float sum = s0 + s1;
#pragma unroll
    for (int off = 16; off > 0; off >>= 1)
        sum += __shfl_xor_sync(0xffffffffu, sum, off);

    if (lid == 0)
        out[b * NK + kdir] = has_valid ? (sum + bk) : 0.f;
}

extern "C" void kernel_launch(void* const* d_in, const int* in_sizes, int n_in,
                              void* d_out, int out_size) {
    const float* hs        = (const float*)d_in[0];
    const float* W         = (const float*)d_in[1];
    const float* bias      = (const float*)d_in[2];
    const int*   input_ids = (const int*)d_in[3];
    const int*   attn_mask = (const int*)d_in[4];
    const int*   token_ids = (const int*)d_in[5];
    float*       out       = (float*)d_out;

    dim3 grid(NK, 32);
    query_token_probe_kernel<<<grid, NT>>>(hs, W, bias, input_ids, attn_mask,
                                           token_ids, out);
}

// round 16
// speedup vs baseline: 1.0435x; 1.0048x over previous
#include <cuda_runtime.h>

#define NS 2048
#define ND 2048
#define NK 6
#define NT 256   // 8 warps
#define NW (NT / 32)

__global__ __launch_bounds__(NT, 2)
void query_token_probe_kernel(const float* __restrict__ hs,
                              const float* __restrict__ W,
                              const float* __restrict__ bias,
                              const int*   __restrict__ input_ids,
                              const int*   __restrict__ attn_mask,
                              const int*   __restrict__ token_ids,
                              float*       __restrict__ out) {
    const int kdir = blockIdx.x;   // 0..5  direction
    const int b    = blockIdx.y;   // 0..31 batch
    const int tid  = threadIdx.x;
    const int wid  = tid >> 5;
    const int lid  = tid & 31;

    __shared__ int s_part[2][NW];  // [lv | lm][warp]

    // this block's token id + bias (tiny scalar loads, overlap the big RT)
    const int   tkv = token_ids[kdir];
    const float bk  = bias[kdir];

    // --- Phase 1: 8 elements per thread, all 4 vector loads independent -> one RT ---
    const int4* mbase = (const int4*)(attn_mask + (size_t)b * NS);
    const int4* ibase = (const int4*)(input_ids + (size_t)b * NS);
    const int4 m4a = mbase[tid];
    const int4 i4a = ibase[tid];
    const int4 m4b = mbase[tid + NT];
    const int4 i4b = ibase[tid + NT];

    int lv = -1;   // last valid position this thread saw
    int lm = -1;   // last position matching tkv

    const int mv[8] = {m4a.x, m4a.y, m4a.z, m4a.w, m4b.x, m4b.y, m4b.z, m4b.w};
    const int iv[8] = {i4a.x, i4a.y, i4a.z, i4a.w, i4b.x, i4b.y, i4b.z, i4b.w};
#pragma unroll
    for (int j = 0; j < 8; j++) {
        const int p = (j < 4) ? (tid * 4 + j) : ((tid + NT) * 4 + (j - 4));
        if (mv[j] > 0) {
            lv = p;                       // p increasing in j -> overwrite == max
            if (iv[j] == tkv) lm = p;
        }
    }

    lv = __reduce_max_sync(0xffffffffu, lv);
    lm = __reduce_max_sync(0xffffffffu, lm);
    if (lid == 0) { s_part[0][wid] = lv; s_part[1][wid] = lm; }
    __syncthreads();                      // the ONLY barrier

    if (wid != 0) return;                 // warp 0 finishes alone

    // cross-warp max: 8 partials in lanes 0..7, one REDUX each
    const int pvv   = (lid < NW) ? s_part[0][lid] : -1;
    const int pv    = (lid < NW) ? s_part[1][lid] : -1;
    const int lastv = __reduce_max_sync(0xffffffffu, pvv);
    int       fp    = __reduce_max_sync(0xffffffffu, pv);
    if (fp < 0) fp = lastv;
    const int  pos       = fp < 0 ? 0 : (fp > NS - 1 ? NS - 1 : fp);
    const bool has_valid = (lastv >= 0);

    // --- Phase 2: full dot by warp 0: 16 hs + 16 W loads, one RT ---
    const float4* __restrict__ hrow =
        (const float4*)(hs + ((size_t)b * NS + (size_t)pos) * ND);
    const float4* __restrict__ wrow = (const float4*)(W + (size_t)kdir * ND);

    float s0 = 0.f, s1 = 0.f;
#pragma unroll
    for (int j = 0; j < 16; j += 2) {
        const float4 h0 = hrow[j * 32 + lid];
        const float4 w0 = wrow[j * 32 + lid];
        const float4 h1 = hrow[(j + 1) * 32 + lid];
        const float4 w1 = wrow[(j + 1) * 32 + lid];
        s0 += h0.x * w0.x + h0.y * w0.y + h0.z * w0.z + h0.w * w0.w;
        s1 += h1.x * w1.x + h1.y * w1.y + h1.z * w1.z + h1.w * w1.w;
    }
    float sum = s0 + s1;
#pragma unroll
    for (int off = 16; off > 0; off >>= 1)
        sum += __shfl_xor_sync(0xffffffffu, sum, off);

    if (lid == 0)
        out[b * NK + kdir] = has_valid ? (sum + bk) : 0.f;
}

extern "C" void kernel_launch(void* const* d_in, const int* in_sizes, int n_in,
                              void* d_out, int out_size) {
    const float* hs        = (const float*)d_in[0];
    const float* W         = (const float*)d_in[1];
    const float* bias      = (const float*)d_in[2];
    const int*   input_ids = (const int*)d_in[3];
    const int*   attn_mask = (const int*)d_in[4];
    const int*   token_ids = (const int*)d_in[5];
    float*       out       = (float*)d_out;

    dim3 grid(NK, 32);
    query_token_probe_kernel<<<grid, NT>>>(hs, W, bias, input_ids, attn_mask,
                                           token_ids, out);
}